// round 8
// baseline (speedup 1.0000x reference)
#include <cuda_runtime.h>
#include <cuda_bf16.h>
#include <math.h>

// DecodeSBP: per-keypoint argmax over sigmoid heatmaps.
// x: [1, 133, 512, 512] fp32.  out: [133,3] = (x*4, y*4, conf) or (-4,-4,-1).
// sigmoid monotonic -> argmax(sigmoid) == argmax; sigmoid only on the max.
//
// Single wave: 148 CTAs x 1024 threads, flat EQUAL segments (58894 float4)
// -> perfect balance + full SM coverage (R1 lost 10% to 133/148 coverage;
// R6 lost to 1.8 ragged waves). Segments decompose into 8192-aligned groups;
// 8192 | 65536 so each aligned group lies in ONE keypoint -> keypoint choice
// is a UNIFORM per-group branch AFTER the unconditional 8-batched LDG.128s
// (the R4 per-element branch that killed batching is gone). Prologue/epilogue
// are single-keypoint by the same alignment and use predicated batched loads.
// Merge: 64-bit key (monotonic float bits << 32 | ~idx) block-reduced and
// atomicMax'd into g_best[k] -> max value, smallest index on ties.

#define KPTS   133
#define HW     (512 * 512)           // 2^18 elems per keypoint
#define HW4    65536                 // 2^16 float4 per keypoint
#define W      512
#define SCALE  4.0f
#define CONF_THRESHOLD 0.8f

#define NT     1024
#define GRID   148
#define N4     (KPTS * HW4)          // 8,716,288 float4
#define SEG    58894                 // ceil(N4/148); last CTA gets 58,870
#define GV     8192                  // group = NT*UB float4; divides HW4
#define UB     8

__device__ unsigned long long g_best[KPTS];   // zero-init: loses to any finite value
__device__ unsigned int g_count = 0;

__device__ __forceinline__ unsigned int float_to_key(float f) {
    unsigned int u = __float_as_uint(f);
    return u ^ ((unsigned int)((int)u >> 31) | 0x80000000u);
}
__device__ __forceinline__ float key_to_float(unsigned int k) {
    unsigned int u = (k & 0x80000000u) ? (k ^ 0x80000000u) : ~k;
    return __uint_as_float(u);
}

// Block-reduce (best, global elem idx) and atomicMax into g_best[k].
__device__ __forceinline__ void flush_kpt(float best, int gidx, int k,
                                          unsigned long long* s_key) {
    const int local = gidx - (k << 18);
    unsigned long long key =
        ((unsigned long long)float_to_key(best) << 32) | (unsigned int)(~local);
    #pragma unroll
    for (int off = 16; off > 0; off >>= 1) {
        unsigned long long o = __shfl_down_sync(0xFFFFFFFFu, key, off);
        if (o > key) key = o;
    }
    const int tid = threadIdx.x, lane = tid & 31, wid = tid >> 5;
    if (lane == 0) s_key[wid] = key;
    __syncthreads();
    if (tid == 0) {
        #pragma unroll
        for (int w = 1; w < NT / 32; w++)
            if (s_key[w] > key) key = s_key[w];
        atomicMax(&g_best[k], key);
    }
    __syncthreads();
}

#define CMP(ACC, IDX, VV, BB)                                   \
    do {                                                        \
        if ((VV).x > (ACC)) { (ACC) = (VV).x; (IDX) = (BB);   } \
        if ((VV).y > (ACC)) { (ACC) = (VV).y; (IDX) = (BB)+1; } \
        if ((VV).z > (ACC)) { (ACC) = (VV).z; (IDX) = (BB)+2; } \
        if ((VV).w > (ACC)) { (ACC) = (VV).w; (IDX) = (BB)+3; } \
    } while (0)

__global__ __launch_bounds__(NT, 1)
void decode_sbp_kernel(const float* __restrict__ x, float* __restrict__ out) {
    const float4* __restrict__ p4 = reinterpret_cast<const float4*>(x);
    __shared__ unsigned long long s_key[NT / 32];
    __shared__ int s_last;

    const int tid = threadIdx.x;
    const int s   = blockIdx.x * SEG;
    const int e   = min(s + SEG, N4);
    const int k0  = s >> 16;
    const int k1  = (e - 1) >> 16;
    const int p   = (s + GV - 1) & ~(GV - 1);   // first aligned group start
    const int q   = e & ~(GV - 1);              // end of last full aligned group

    const float4 NEG4 = make_float4(-INFINITY, -INFINITY, -INFINITY, -INFINITY);

    float bestA = -INFINITY; int idxA = 0;      // keypoint k0
    float bestB = -INFINITY; int idxB = 0;      // keypoint k1 (if != k0)

    // ---- Prologue [s, p): inside one aligned block -> keypoint k0. ----
    if (p > s) {
        float4 v[UB];
        #pragma unroll
        for (int u = 0; u < UB; u++) {
            const int j = s + tid + u * NT;
            v[u] = (j < p) ? p4[j] : NEG4;
        }
        #pragma unroll
        for (int u = 0; u < UB; u++) {
            const int b = (s + tid + u * NT) << 2;
            CMP(bestA, idxA, v[u], b);
        }
    }

    // ---- Main: full aligned groups; each group is in exactly one keypoint. ----
    for (int g = p; g < q; g += GV) {
        float4 v[UB];
        #pragma unroll
        for (int u = 0; u < UB; u++)
            v[u] = p4[g + tid + u * NT];        // unconditional, batched
        if ((g >> 16) == k0) {                  // uniform across the CTA
            #pragma unroll
            for (int u = 0; u < UB; u++) {
                const int b = (g + tid + u * NT) << 2;
                CMP(bestA, idxA, v[u], b);
            }
        } else {
            #pragma unroll
            for (int u = 0; u < UB; u++) {
                const int b = (g + tid + u * NT) << 2;
                CMP(bestB, idxB, v[u], b);
            }
        }
    }

    // ---- Epilogue [q, e): inside one aligned block -> keypoint k1. ----
    if (e > q) {
        float4 v[UB];
        #pragma unroll
        for (int u = 0; u < UB; u++) {
            const int j = q + tid + u * NT;
            v[u] = (j < e) ? p4[j] : NEG4;
        }
        if (k1 == k0) {
            #pragma unroll
            for (int u = 0; u < UB; u++) {
                const int b = (q + tid + u * NT) << 2;
                CMP(bestA, idxA, v[u], b);
            }
        } else {
            #pragma unroll
            for (int u = 0; u < UB; u++) {
                const int b = (q + tid + u * NT) << 2;
                CMP(bestB, idxB, v[u], b);
            }
        }
    }

    // Per-thread visit order within each keypoint is ascending -> strict '>'
    // preserves first-occurrence; cross-thread ties resolved by ~idx in key.
    flush_kpt(bestA, idxA, k0, s_key);
    if (k1 != k0) flush_kpt(bestB, idxB, k1, s_key);

    if (tid == 0) {
        __threadfence();
        unsigned int old = atomicAdd(&g_count, 1u);
        s_last = (old == GRID - 1) ? 1 : 0;
    }
    __syncthreads();

    if (s_last) {
        __threadfence();
        if (tid < KPTS) {
            const unsigned long long m = g_best[tid];
            const float mv  = key_to_float((unsigned int)(m >> 32));
            const int   idx = (int)~(unsigned int)(m & 0xFFFFFFFFu);
            const float conf = 1.0f / (1.0f + __expf(-mv));
            const bool valid = conf > CONF_THRESHOLD;
            const float yy = (float)(idx / W);
            const float xx = (float)(idx % W);
            out[tid * 3 + 0] = valid ? xx * SCALE : -SCALE;
            out[tid * 3 + 1] = valid ? yy * SCALE : -SCALE;
            out[tid * 3 + 2] = valid ? conf : -1.0f;
            g_best[tid] = 0ull;      // reset for next graph replay
        }
        if (tid == 0) g_count = 0;
    }
}

extern "C" void kernel_launch(void* const* d_in, const int* in_sizes, int n_in,
                              void* d_out, int out_size) {
    const float* x = (const float*)d_in[0];
    float* out = (float*)d_out;
    decode_sbp_kernel<<<GRID, NT>>>(x, out);
}

// round 9
// speedup vs baseline: 1.0705x; 1.0705x over previous
#include <cuda_runtime.h>
#include <cuda_bf16.h>
#include <math.h>

// DecodeSBP: per-keypoint argmax over sigmoid heatmaps.
// x: [1, 133, 512, 512] fp32.  out: [133,3] = (x*4, y*4, conf) or (-4,-4,-1).
// sigmoid monotonic -> argmax(sigmoid) == argmax; sigmoid only on the max.
//
// Round-9 design = Round-1 (best: 25.3us, DRAM 74%) with exactly two deltas:
//   1. explicit 8-batched LDG.128 groups (only change that measurably raised
//      DRAM% across rounds 2-8),
//   2. __ldcs streaming loads (zero reuse -> evict-first).
// Everything else identical: one CTA per keypoint (133 x 1024), literal
// trip counts, branch-free body, direct output write, no global merge state.
// Rounds 2-8 established that filling the 15 idle SMs with flat segments,
// chunked grids, or boundary logic costs MORE than the idle SMs do.

#define KPTS   133
#define HW     (512 * 512)
#define HW4    65536               // float4 per keypoint
#define W      512
#define SCALE  4.0f
#define CONF_THRESHOLD 0.8f

#define NT     1024
#define UB     8                   // batched loads per group
#define GROUPS (HW4 / (NT * UB))   // 8 groups x 8 loads = 64 iters (as R1)

__global__ __launch_bounds__(NT, 1)
void decode_sbp_kernel(const float* __restrict__ x, float* __restrict__ out) {
    const int k = blockIdx.x;
    const float4* __restrict__ p =
        reinterpret_cast<const float4*>(x + (size_t)k * HW);

    const int tid = threadIdx.x;

    float best = -INFINITY;
    int bidx = 0;

    // 8 groups x (8 back-to-back streaming LDG.128 -> compares).
    // Indices strictly increase per thread -> strict '>' keeps the first
    // occurrence, matching jnp.argmax row-major tie-break.
    #pragma unroll
    for (int g = 0; g < GROUPS; g++) {
        const int base = g * (NT * UB) + tid;
        float4 v[UB];
        #pragma unroll
        for (int u = 0; u < UB; u++)
            v[u] = __ldcs(p + base + u * NT);
        #pragma unroll
        for (int u = 0; u < UB; u++) {
            const int b = (base + u * NT) << 2;
            if (v[u].x > best) { best = v[u].x; bidx = b;     }
            if (v[u].y > best) { best = v[u].y; bidx = b + 1; }
            if (v[u].z > best) { best = v[u].z; bidx = b + 2; }
            if (v[u].w > best) { best = v[u].w; bidx = b + 3; }
        }
    }

    // Warp reduction: max value, ties -> smaller index (first occurrence).
    #pragma unroll
    for (int off = 16; off > 0; off >>= 1) {
        float v2 = __shfl_down_sync(0xFFFFFFFFu, best, off);
        int   i2 = __shfl_down_sync(0xFFFFFFFFu, bidx, off);
        if (v2 > best || (v2 == best && i2 < bidx)) { best = v2; bidx = i2; }
    }

    __shared__ float s_val[NT / 32];
    __shared__ int   s_idx[NT / 32];

    const int lane = tid & 31;
    const int wid  = tid >> 5;
    if (lane == 0) { s_val[wid] = best; s_idx[wid] = bidx; }
    __syncthreads();

    if (wid == 0) {
        best = s_val[lane];
        bidx = s_idx[lane];
        #pragma unroll
        for (int off = 16; off > 0; off >>= 1) {
            float v2 = __shfl_down_sync(0xFFFFFFFFu, best, off);
            int   i2 = __shfl_down_sync(0xFFFFFFFFu, bidx, off);
            if (v2 > best || (v2 == best && i2 < bidx)) { best = v2; bidx = i2; }
        }
        if (lane == 0) {
            const float conf = 1.0f / (1.0f + __expf(-best));
            const bool valid = conf > CONF_THRESHOLD;
            const float yy = (float)(bidx / W);
            const float xx = (float)(bidx % W);
            // Invalid rows: (-1,-1,-1) then x,y scaled -> (-4,-4,-1).
            out[k * 3 + 0] = valid ? xx * SCALE : -SCALE;
            out[k * 3 + 1] = valid ? yy * SCALE : -SCALE;
            out[k * 3 + 2] = valid ? conf : -1.0f;
        }
    }
}

extern "C" void kernel_launch(void* const* d_in, const int* in_sizes, int n_in,
                              void* d_out, int out_size) {
    const float* x = (const float*)d_in[0];
    float* out = (float*)d_out;
    decode_sbp_kernel<<<KPTS, NT>>>(x, out);
}